// round 8
// baseline (speedup 1.0000x reference)
#include <cuda_runtime.h>
#include <math_constants.h>

#define H 1024
#define S 32768
#define GRID 296                 // 148 SMs x occ 2, all slots filled
#define BLK 256
#define TILE_ROWS 8
#define NTILES_TOT (S / TILE_ROWS)        // 4096
#define STAGES 3
#define TILE_BYTES (TILE_ROWS * H * 4)    // 32768
#define TILE_F4 (TILE_ROWS * H / 4)       // 2048
#define SMEM_DYN (STAGES * TILE_BYTES)    // 98304
#define NSLICES 256                       // P0: 4 d-rows per slice
#define MAX_TILES_BLK 14

// Scratch (no allocations allowed)
__device__ float g_vpart[NSLICES * H];    // 1 MB
__device__ float g_v[H];
__device__ float g_bmax[GRID];
__device__ float g_bsum[GRID];
__device__ unsigned g_bar;   // zero-init; self-resetting
__device__ unsigned g_done;

__device__ __forceinline__ void grid_sync(unsigned target) {
    __syncthreads();
    __threadfence();
    if (threadIdx.x == 0) {
        atomicAdd(&g_bar, 1u);
        while (*(volatile unsigned*)&g_bar < target) __nanosleep(64);
    }
    __syncthreads();
}

__device__ __forceinline__ void mbar_wait(unsigned mbar, unsigned parity) {
    asm volatile(
        "{\n\t"
        ".reg .pred P;\n\t"
        "W_%=:\n\t"
        "mbarrier.try_wait.parity.acquire.cta.shared::cta.b64 P, [%0], %1, 0x989680;\n\t"
        "@P bra D_%=;\n\t"
        "bra W_%=;\n\t"
        "D_%=:\n\t"
        "}" :: "r"(mbar), "r"(parity) : "memory");
}

__device__ __forceinline__ void bulk_fetch(unsigned ba, float4* dst,
                                           const char* src) {
    asm volatile("mbarrier.arrive.expect_tx.shared.b64 _, [%0], %1;"
                 :: "r"(ba), "r"(TILE_BYTES) : "memory");
    unsigned da = (unsigned)__cvta_generic_to_shared(dst);
    asm volatile("cp.async.bulk.shared::cta.global.mbarrier::complete_tx::bytes "
                 "[%0], [%1], %2, [%3];"
                 :: "r"(da), "l"(src), "r"(TILE_BYTES), "r"(ba) : "memory");
}

__global__ __launch_bounds__(BLK, 2) void fused_kernel(
    const float* __restrict__ W,
    const float* __restrict__ hidden,
    const float* __restrict__ enc,
    float* __restrict__ out)
{
    extern __shared__ float4 tile[];                   // [STAGES][TILE_F4]
    __shared__ __align__(8) unsigned long long mbar[STAGES];
    __shared__ float s_sc[MAX_TILES_BLK * TILE_ROWS];  // up to 112 scores
    __shared__ float red[BLK];

    const int tid  = threadIdx.x;
    const int warp = tid >> 5;
    const int lane = tid & 31;
    const int b    = blockIdx.x;

    const int tile_begin = (b * NTILES_TOT) / GRID;
    const int tile_end   = ((b + 1) * NTILES_TOT) / GRID;
    const int ntiles     = tile_end - tile_begin;      // 13 or 14

    const char* encb = reinterpret_cast<const char*>(enc);

    // ---- mbarrier init + kick off the enc pipeline IMMEDIATELY ------------
    if (tid == 0) {
#pragma unroll
        for (int s = 0; s < STAGES; s++) {
            unsigned a = (unsigned)__cvta_generic_to_shared(&mbar[s]);
            asm volatile("mbarrier.init.shared.b64 [%0], 1;" :: "r"(a) : "memory");
        }
        asm volatile("fence.proxy.async.shared::cta;" ::: "memory");
#pragma unroll
        for (int s = 0; s < STAGES; s++) {
            unsigned ba = (unsigned)__cvta_generic_to_shared(&mbar[s]);
            bulk_fetch(ba, tile + s * TILE_F4,
                       encb + (size_t)(tile_begin + s) * TILE_BYTES);
        }
    }

    // ---- P0: W partials (256 of 296 blocks, 4 d-rows each) ----------------
    // Runs concurrently with the in-flight enc bulk copies.
    if (b < NSLICES) {
        const int d0 = b * (H / NSLICES);
        float acc0 = 0.f, acc1 = 0.f, acc2 = 0.f, acc3 = 0.f;
#pragma unroll
        for (int dd = 0; dd < H / NSLICES; dd++) {
            const float hd = __ldg(&hidden[d0 + dd]);
            const float* wr = W + (size_t)(d0 + dd) * H;
            acc0 += wr[tid      ] * hd;
            acc1 += wr[tid + 256] * hd;
            acc2 += wr[tid + 512] * hd;
            acc3 += wr[tid + 768] * hd;
        }
        g_vpart[b * H + tid      ] = acc0;
        g_vpart[b * H + tid + 256] = acc1;
        g_vpart[b * H + tid + 512] = acc2;
        g_vpart[b * H + tid + 768] = acc3;
    }
    grid_sync(GRID);

    // ---- P1: reduce 256 partials -> g_v (4 blocks, coalesced) -------------
    if (b < 4) {
        const int h = b * 256 + tid;
        float acc = 0.f;
#pragma unroll 8
        for (int i = 0; i < NSLICES; i++) acc += g_vpart[i * H + h];
        g_v[h] = acc;
    }
    grid_sync(2 * GRID);

    // ---- P2: consume the pipeline -----------------------------------------
    float4 vr[8];
    const float4* v4 = reinterpret_cast<const float4*>(g_v);
#pragma unroll
    for (int k = 0; k < 8; k++) vr[k] = v4[lane + k * 32];

#pragma unroll 1
    for (int t = 0; t < ntiles; t++) {
        const int st = t % STAGES;
        unsigned ba = (unsigned)__cvta_generic_to_shared(&mbar[st]);
        mbar_wait(ba, (t / STAGES) & 1);

        const float4* rowp = tile + st * TILE_F4 + warp * (H / 4);
        float acc = 0.f;
#pragma unroll
        for (int k = 0; k < 8; k++) {
            float4 e = rowp[lane + k * 32];
            acc += e.x * vr[k].x + e.y * vr[k].y + e.z * vr[k].z + e.w * vr[k].w;
        }
#pragma unroll
        for (int o = 16; o > 0; o >>= 1) acc += __shfl_xor_sync(0xFFFFFFFFu, acc, o);
        if (lane == 0) s_sc[t * TILE_ROWS + warp] = acc;

        __syncthreads();   // all warps done reading stage st
        if (tid == 0 && t + STAGES < ntiles) {
            bulk_fetch(ba, tile + st * TILE_F4,
                       encb + (size_t)(tile_begin + t + STAGES) * TILE_BYTES);
        }
    }

    // ---- block (max, expsum) over its nrows scores ------------------------
    const int nrows = ntiles * TILE_ROWS;             // 104 or 112
    red[tid] = (tid < nrows) ? s_sc[tid] : -CUDART_INF_F;
    __syncthreads();
#pragma unroll
    for (int s = 128; s > 0; s >>= 1) {
        if (tid < s) red[tid] = fmaxf(red[tid], red[tid + s]);
        __syncthreads();
    }
    const float Mb = red[0];
    __syncthreads();
    red[tid] = (tid < nrows) ? __expf(s_sc[tid] - Mb) : 0.f;
    __syncthreads();
#pragma unroll
    for (int s = 128; s > 0; s >>= 1) {
        if (tid < s) red[tid] += red[tid + s];
        __syncthreads();
    }
    if (tid == 0) {
        g_bmax[b] = Mb;
        g_bsum[b] = red[0];
    }
    grid_sync(3 * GRID);

    // ---- P3: redundant pair-reduce (296 pairs) + normalize ----------------
    const float pm0 = g_bmax[tid];
    const float ps0 = g_bsum[tid];
    float pm1 = -CUDART_INF_F, ps1 = 0.f;
    if (tid < GRID - BLK) {                           // tid < 40
        pm1 = g_bmax[tid + BLK];
        ps1 = g_bsum[tid + BLK];
    }
    red[tid] = fmaxf(pm0, pm1);
    __syncthreads();
#pragma unroll
    for (int s = 128; s > 0; s >>= 1) {
        if (tid < s) red[tid] = fmaxf(red[tid], red[tid + s]);
        __syncthreads();
    }
    const float M = red[0];
    __syncthreads();
    red[tid] = ps0 * __expf(pm0 - M) + ps1 * __expf(pm1 - M);
    __syncthreads();
#pragma unroll
    for (int s = 128; s > 0; s >>= 1) {
        if (tid < s) red[tid] += red[tid + s];
        __syncthreads();
    }
    const float inv = 1.0f / red[0];

    if (tid < nrows)
        out[tile_begin * TILE_ROWS + tid] = __expf(s_sc[tid] - M) * inv;

    // ---- reset counters for next graph replay -----------------------------
    __threadfence();
    __syncthreads();
    if (tid == 0) {
        unsigned d = atomicAdd(&g_done, 1u) + 1;
        if (d == GRID) {
            g_bar = 0;
            g_done = 0;
            __threadfence();
        }
    }
}

// ---------------------------------------------------------------------------
extern "C" void kernel_launch(void* const* d_in, const int* in_sizes, int n_in,
                              void* d_out, int out_size) {
    const float* hidden = (const float*)d_in[0];   // [H]
    const float* enc    = (const float*)d_in[1];   // [S, H]
    const float* W      = (const float*)d_in[2];   // [H, H]
    float* out          = (float*)d_out;           // [S]

    cudaFuncSetAttribute(fused_kernel,
                         cudaFuncAttributeMaxDynamicSharedMemorySize, SMEM_DYN);
    fused_kernel<<<GRID, BLK, SMEM_DYN>>>(W, hidden, enc, out);
}

// round 9
// speedup vs baseline: 1.1218x; 1.1218x over previous
#include <cuda_runtime.h>
#include <math_constants.h>

#define H 1024
#define S 32768
#define GRID 296                 // 148 SMs x occ 2, all slots filled
#define BLK 256
#define TILE_ROWS 8
#define NTILES_TOT (S / TILE_ROWS)        // 4096
#define STAGES 3
#define TILE_BYTES (TILE_ROWS * H * 4)    // 32768
#define TILE_F4 (TILE_ROWS * H / 4)       // 2048
#define SMEM_DYN (STAGES * TILE_BYTES)    // 98304
#define NSLICES 128                       // P0: 8 d-rows per slice
#define MAX_TILES_BLK 14

// Scratch (no allocations allowed)
__device__ float g_vpart[NSLICES * H];    // 512 KB
__device__ float g_v[H];
__device__ float g_bmax[GRID];
__device__ float g_bsum[GRID];
__device__ unsigned g_bar;   // zero-init; self-resetting
__device__ unsigned g_done;

__device__ __forceinline__ void grid_sync(unsigned target) {
    __syncthreads();
    __threadfence();
    if (threadIdx.x == 0) {
        atomicAdd(&g_bar, 1u);
        while (*(volatile unsigned*)&g_bar < target) __nanosleep(64);
    }
    __syncthreads();
}

__device__ __forceinline__ void mbar_wait(unsigned mbar, unsigned parity) {
    asm volatile(
        "{\n\t"
        ".reg .pred P;\n\t"
        "W_%=:\n\t"
        "mbarrier.try_wait.parity.acquire.cta.shared::cta.b64 P, [%0], %1, 0x989680;\n\t"
        "@P bra D_%=;\n\t"
        "bra W_%=;\n\t"
        "D_%=:\n\t"
        "}" :: "r"(mbar), "r"(parity) : "memory");
}

__device__ __forceinline__ void bulk_fetch(unsigned ba, float4* dst,
                                           const char* src) {
    asm volatile("mbarrier.arrive.expect_tx.shared.b64 _, [%0], %1;"
                 :: "r"(ba), "r"(TILE_BYTES) : "memory");
    unsigned da = (unsigned)__cvta_generic_to_shared(dst);
    asm volatile("cp.async.bulk.shared::cta.global.mbarrier::complete_tx::bytes "
                 "[%0], [%1], %2, [%3];"
                 :: "r"(da), "l"(src), "r"(TILE_BYTES), "r"(ba) : "memory");
}

__global__ __launch_bounds__(BLK, 2) void fused_kernel(
    const float* __restrict__ W,
    const float* __restrict__ hidden,
    const float* __restrict__ enc,
    float* __restrict__ out)
{
    extern __shared__ float4 tile[];                   // [STAGES][TILE_F4]
    __shared__ __align__(8) unsigned long long mbar[STAGES];
    __shared__ float s_sc[MAX_TILES_BLK * TILE_ROWS];  // up to 112 scores
    __shared__ float red[BLK];

    const int tid  = threadIdx.x;
    const int warp = tid >> 5;
    const int lane = tid & 31;
    const int b    = blockIdx.x;

    const int tile_begin = (b * NTILES_TOT) / GRID;
    const int tile_end   = ((b + 1) * NTILES_TOT) / GRID;
    const int ntiles     = tile_end - tile_begin;      // 13 or 14

    const char* encb = reinterpret_cast<const char*>(enc);

    // ---- mbarrier init + kick off the enc pipeline IMMEDIATELY ------------
    if (tid == 0) {
#pragma unroll
        for (int s = 0; s < STAGES; s++) {
            unsigned a = (unsigned)__cvta_generic_to_shared(&mbar[s]);
            asm volatile("mbarrier.init.shared.b64 [%0], 1;" :: "r"(a) : "memory");
        }
        asm volatile("fence.proxy.async.shared::cta;" ::: "memory");
#pragma unroll
        for (int s = 0; s < STAGES; s++) {
            unsigned ba = (unsigned)__cvta_generic_to_shared(&mbar[s]);
            bulk_fetch(ba, tile + s * TILE_F4,
                       encb + (size_t)(tile_begin + s) * TILE_BYTES);
        }
    }

    // ---- P0: W partials (128 blocks x 8 d-rows), overlapped with TMA ------
    if (b < NSLICES) {
        const int d0 = b * (H / NSLICES);
        float acc0 = 0.f, acc1 = 0.f, acc2 = 0.f, acc3 = 0.f;
#pragma unroll
        for (int dd = 0; dd < H / NSLICES; dd++) {
            const float hd = __ldg(&hidden[d0 + dd]);
            const float* wr = W + (size_t)(d0 + dd) * H;
            acc0 += wr[tid      ] * hd;
            acc1 += wr[tid + 256] * hd;
            acc2 += wr[tid + 512] * hd;
            acc3 += wr[tid + 768] * hd;
        }
        g_vpart[b * H + tid      ] = acc0;
        g_vpart[b * H + tid + 256] = acc1;
        g_vpart[b * H + tid + 512] = acc2;
        g_vpart[b * H + tid + 768] = acc3;
    }
    grid_sync(GRID);

    // ---- P1: reduce 128 partials -> g_v (128 blocks, warp per h) ----------
    if (b < 128) {
        const int h = b * 8 + warp;
        float a = 0.f;
#pragma unroll
        for (int k = 0; k < NSLICES / 32; k++)         // 4 loads per lane
            a += g_vpart[(lane + k * 32) * H + h];
#pragma unroll
        for (int o = 16; o > 0; o >>= 1) a += __shfl_xor_sync(0xFFFFFFFFu, a, o);
        if (lane == 0) g_v[h] = a;
    }
    grid_sync(2 * GRID);

    // ---- P2: consume the pipeline -----------------------------------------
    float4 vr[8];
    const float4* v4 = reinterpret_cast<const float4*>(g_v);
#pragma unroll
    for (int k = 0; k < 8; k++) vr[k] = v4[lane + k * 32];

#pragma unroll 1
    for (int t = 0; t < ntiles; t++) {
        const int st = t % STAGES;
        unsigned ba = (unsigned)__cvta_generic_to_shared(&mbar[st]);
        mbar_wait(ba, (t / STAGES) & 1);

        const float4* rowp = tile + st * TILE_F4 + warp * (H / 4);
        float acc = 0.f;
#pragma unroll
        for (int k = 0; k < 8; k++) {
            float4 e = rowp[lane + k * 32];
            acc += e.x * vr[k].x + e.y * vr[k].y + e.z * vr[k].z + e.w * vr[k].w;
        }
#pragma unroll
        for (int o = 16; o > 0; o >>= 1) acc += __shfl_xor_sync(0xFFFFFFFFu, acc, o);
        if (lane == 0) s_sc[t * TILE_ROWS + warp] = acc;

        __syncthreads();   // all warps done reading stage st
        if (tid == 0 && t + STAGES < ntiles) {
            bulk_fetch(ba, tile + st * TILE_F4,
                       encb + (size_t)(tile_begin + t + STAGES) * TILE_BYTES);
        }
    }

    // ---- block (max, expsum) over its nrows scores ------------------------
    const int nrows = ntiles * TILE_ROWS;             // 104 or 112
    red[tid] = (tid < nrows) ? s_sc[tid] : -CUDART_INF_F;
    __syncthreads();
#pragma unroll
    for (int s = 128; s > 0; s >>= 1) {
        if (tid < s) red[tid] = fmaxf(red[tid], red[tid + s]);
        __syncthreads();
    }
    const float Mb = red[0];
    __syncthreads();
    red[tid] = (tid < nrows) ? __expf(s_sc[tid] - Mb) : 0.f;
    __syncthreads();
#pragma unroll
    for (int s = 128; s > 0; s >>= 1) {
        if (tid < s) red[tid] += red[tid + s];
        __syncthreads();
    }
    if (tid == 0) {
        g_bmax[b] = Mb;
        g_bsum[b] = red[0];
    }
    grid_sync(3 * GRID);

    // ---- P3: redundant pair-reduce (296 pairs) + normalize ----------------
    const float pm0 = g_bmax[tid];
    const float ps0 = g_bsum[tid];
    float pm1 = -CUDART_INF_F, ps1 = 0.f;
    if (tid < GRID - BLK) {                           // tid < 40
        pm1 = g_bmax[tid + BLK];
        ps1 = g_bsum[tid + BLK];
    }
    red[tid] = fmaxf(pm0, pm1);
    __syncthreads();
#pragma unroll
    for (int s = 128; s > 0; s >>= 1) {
        if (tid < s) red[tid] = fmaxf(red[tid], red[tid + s]);
        __syncthreads();
    }
    const float M = red[0];
    __syncthreads();
    red[tid] = ps0 * __expf(pm0 - M) + ps1 * __expf(pm1 - M);
    __syncthreads();
#pragma unroll
    for (int s = 128; s > 0; s >>= 1) {
        if (tid < s) red[tid] += red[tid + s];
        __syncthreads();
    }
    const float inv = 1.0f / red[0];

    if (tid < nrows)
        out[tile_begin * TILE_ROWS + tid] = __expf(s_sc[tid] - M) * inv;

    // ---- reset counters for next graph replay -----------------------------
    __threadfence();
    __syncthreads();
    if (tid == 0) {
        unsigned d = atomicAdd(&g_done, 1u) + 1;
        if (d == GRID) {
            g_bar = 0;
            g_done = 0;
            __threadfence();
        }
    }
}

// ---------------------------------------------------------------------------
extern "C" void kernel_launch(void* const* d_in, const int* in_sizes, int n_in,
                              void* d_out, int out_size) {
    const float* hidden = (const float*)d_in[0];   // [H]
    const float* enc    = (const float*)d_in[1];   // [S, H]
    const float* W      = (const float*)d_in[2];   // [H, H]
    float* out          = (float*)d_out;           // [S]

    cudaFuncSetAttribute(fused_kernel,
                         cudaFuncAttributeMaxDynamicSharedMemorySize, SMEM_DYN);
    fused_kernel<<<GRID, BLK, SMEM_DYN>>>(W, hidden, enc, out);
}

// round 10
// speedup vs baseline: 1.1449x; 1.0206x over previous
#include <cuda_runtime.h>
#include <math_constants.h>

#define H 1024
#define S 32768
#define GRID 256
#define BLK 256
#define TILE_ROWS 8                      // logical tile: 8 rows
#define NTILES 16                        // tiles per block (128 rows/block)
#define ROWS_PER_BLK (TILE_ROWS * NTILES)
#define STAGES 4
#define HTILE_BYTES (4 * H * 4)          // TMA half-tile: 4 rows = 16 KB
#define HTILE_F4 (4 * H / 4)             // 1024 float4
#define SMEM_DYN (STAGES * HTILE_BYTES)  // 65536
#define D_SLICES 64

// Scratch (no allocations allowed)
__device__ float g_vpart[D_SLICES * H];
__device__ float g_v[H];
__device__ float g_bmax[GRID];
__device__ float g_bsum[GRID];
__device__ unsigned g_bar;   // zero-init; self-resetting
__device__ unsigned g_done;

__device__ __forceinline__ void grid_sync(unsigned target) {
    __syncthreads();
    __threadfence();
    if (threadIdx.x == 0) {
        atomicAdd(&g_bar, 1u);
        while (*(volatile unsigned*)&g_bar < target) __nanosleep(64);
    }
    __syncthreads();
}

__device__ __forceinline__ void mbar_wait(unsigned mbar, unsigned parity) {
    asm volatile(
        "{\n\t"
        ".reg .pred P;\n\t"
        "W_%=:\n\t"
        "mbarrier.try_wait.parity.acquire.cta.shared::cta.b64 P, [%0], %1, 0x989680;\n\t"
        "@P bra D_%=;\n\t"
        "bra W_%=;\n\t"
        "D_%=:\n\t"
        "}" :: "r"(mbar), "r"(parity) : "memory");
}

__device__ __forceinline__ void bulk_fetch(unsigned ba, float4* dst,
                                           const char* src) {
    asm volatile("mbarrier.arrive.expect_tx.shared.b64 _, [%0], %1;"
                 :: "r"(ba), "r"(HTILE_BYTES) : "memory");
    unsigned da = (unsigned)__cvta_generic_to_shared(dst);
    asm volatile("cp.async.bulk.shared::cta.global.mbarrier::complete_tx::bytes "
                 "[%0], [%1], %2, [%3];"
                 :: "r"(da), "l"(src), "r"(HTILE_BYTES), "r"(ba) : "memory");
}

__global__ __launch_bounds__(BLK, 2) void fused_kernel(
    const float* __restrict__ W,
    const float* __restrict__ hidden,
    const float* __restrict__ enc,
    float* __restrict__ out)
{
    extern __shared__ float4 tile[];                   // [STAGES][HTILE_F4]
    __shared__ __align__(8) unsigned long long mbar[STAGES];
    __shared__ float s_sc[ROWS_PER_BLK];               // 128 scores
    __shared__ float red[BLK];

    const int tid  = threadIdx.x;
    const int warp = tid >> 5;
    const int lane = tid & 31;
    const int b    = blockIdx.x;
    const size_t row_base = (size_t)b * ROWS_PER_BLK;

    // mbarrier init (count=1; producer arrives via expect_tx)
    if (tid == 0) {
#pragma unroll
        for (int s = 0; s < STAGES; s++) {
            unsigned a = (unsigned)__cvta_generic_to_shared(&mbar[s]);
            asm volatile("mbarrier.init.shared.b64 [%0], 1;" :: "r"(a) : "memory");
        }
        asm volatile("fence.proxy.async.shared::cta;" ::: "memory");
    }

    // ---------------- P0: v partials (blocks 0..63, coalesced W read) ------
    if (b < D_SLICES) {
        const int d0 = b * (H / D_SLICES);
        float acc0 = 0.f, acc1 = 0.f, acc2 = 0.f, acc3 = 0.f;
#pragma unroll
        for (int dd = 0; dd < H / D_SLICES; dd++) {
            const float hd = __ldg(&hidden[d0 + dd]);
            const float* wr = W + (size_t)(d0 + dd) * H;
            acc0 += wr[tid        ] * hd;
            acc1 += wr[tid +  256 ] * hd;
            acc2 += wr[tid +  512 ] * hd;
            acc3 += wr[tid +  768 ] * hd;
        }
        g_vpart[b * H + tid      ] = acc0;
        g_vpart[b * H + tid + 256] = acc1;
        g_vpart[b * H + tid + 512] = acc2;
        g_vpart[b * H + tid + 768] = acc3;
    }
    grid_sync(GRID);

    // ---------------- P1: reduce partials -> g_v (blocks 0..127) -----------
    if (b < 128) {
        const int h = b * 8 + warp;      // warp per h
        float a = g_vpart[lane * H + h] + g_vpart[(lane + 32) * H + h];
#pragma unroll
        for (int o = 16; o > 0; o >>= 1) a += __shfl_xor_sync(0xFFFFFFFFu, a, o);
        if (lane == 0) g_v[h] = a;
    }
    grid_sync(2 * GRID);

    // ---------------- P2: dual-path stream ---------------------------------
    // v resident in registers (same lane pattern for every row)
    float4 vr[8];
    const float4* v4 = reinterpret_cast<const float4*>(g_v);
#pragma unroll
    for (int k = 0; k < 8; k++) vr[k] = v4[lane + k * 32];

    const char* encb = reinterpret_cast<const char*>(enc);

    if (warp < 4) {
        // ---- TMA path: rows 0-3 of each 8-row tile, smem pipeline ----
        if (tid == 0) {
#pragma unroll
            for (int s = 0; s < STAGES; s++) {
                unsigned ba = (unsigned)__cvta_generic_to_shared(&mbar[s]);
                bulk_fetch(ba, tile + s * HTILE_F4,
                           encb + (row_base + (size_t)s * TILE_ROWS) * (H * 4));
            }
        }
#pragma unroll 1
        for (int t = 0; t < NTILES; t++) {
            const int st = t % STAGES;
            unsigned ba = (unsigned)__cvta_generic_to_shared(&mbar[st]);
            mbar_wait(ba, (t / STAGES) & 1);

            const float4* rowp = tile + st * HTILE_F4 + warp * (H / 4);
            float acc = 0.f;
#pragma unroll
            for (int k = 0; k < 8; k++) {
                float4 e = rowp[lane + k * 32];
                acc += e.x * vr[k].x + e.y * vr[k].y + e.z * vr[k].z + e.w * vr[k].w;
            }
#pragma unroll
            for (int o = 16; o > 0; o >>= 1) acc += __shfl_xor_sync(0xFFFFFFFFu, acc, o);
            if (lane == 0) s_sc[t * TILE_ROWS + warp] = acc;

            // pipeline-group barrier (warps 0-3 only), then refill stage
            asm volatile("bar.sync 1, 128;" ::: "memory");
            if (tid == 0 && t + STAGES < NTILES) {
                bulk_fetch(ba, tile + st * HTILE_F4,
                           encb + (row_base + (size_t)(t + STAGES) * TILE_ROWS) * (H * 4));
            }
        }
    } else {
        // ---- LDG path: rows 4-7 of each tile, free-running, reg-resident --
#pragma unroll 1
        for (int t = 0; t < NTILES; t++) {
            const size_t row = row_base + (size_t)t * TILE_ROWS + warp; // warp 4..7
            const float4* r = reinterpret_cast<const float4*>(enc + row * H);
            float a0 = 0.f, a1 = 0.f, a2 = 0.f, a3 = 0.f;
#pragma unroll
            for (int k = 0; k < 8; k += 4) {
                float4 e0 = r[lane + (k + 0) * 32];
                float4 e1 = r[lane + (k + 1) * 32];
                float4 e2 = r[lane + (k + 2) * 32];
                float4 e3 = r[lane + (k + 3) * 32];
                a0 += e0.x * vr[k+0].x + e0.y * vr[k+0].y + e0.z * vr[k+0].z + e0.w * vr[k+0].w;
                a1 += e1.x * vr[k+1].x + e1.y * vr[k+1].y + e1.z * vr[k+1].z + e1.w * vr[k+1].w;
                a2 += e2.x * vr[k+2].x + e2.y * vr[k+2].y + e2.z * vr[k+2].z + e2.w * vr[k+2].w;
                a3 += e3.x * vr[k+3].x + e3.y * vr[k+3].y + e3.z * vr[k+3].z + e3.w * vr[k+3].w;
            }
            float acc = (a0 + a1) + (a2 + a3);
#pragma unroll
            for (int o = 16; o > 0; o >>= 1) acc += __shfl_xor_sync(0xFFFFFFFFu, acc, o);
            if (lane == 0) s_sc[t * TILE_ROWS + warp] = acc;
        }
    }
    __syncthreads();

    // ---------------- block (max, expsum) over its 128 scores --------------
    red[tid] = (tid < ROWS_PER_BLK) ? s_sc[tid] : -CUDART_INF_F;
    __syncthreads();
#pragma unroll
    for (int s = 128; s > 0; s >>= 1) {
        if (tid < s) red[tid] = fmaxf(red[tid], red[tid + s]);
        __syncthreads();
    }
    const float Mb = red[0];
    __syncthreads();
    red[tid] = (tid < ROWS_PER_BLK) ? __expf(s_sc[tid] - Mb) : 0.f;
    __syncthreads();
#pragma unroll
    for (int s = 128; s > 0; s >>= 1) {
        if (tid < s) red[tid] += red[tid + s];
        __syncthreads();
    }
    if (tid == 0) {
        g_bmax[b] = Mb;
        g_bsum[b] = red[0];
    }
    grid_sync(3 * GRID);

    // ---------------- P3: redundant pair-reduce + normalize ----------------
    const float pm = g_bmax[tid];          // GRID == BLK == 256
    const float ps = g_bsum[tid];
    red[tid] = pm;
    __syncthreads();
#pragma unroll
    for (int s = 128; s > 0; s >>= 1) {
        if (tid < s) red[tid] = fmaxf(red[tid], red[tid + s]);
        __syncthreads();
    }
    const float M = red[0];
    __syncthreads();
    red[tid] = ps * __expf(pm - M);
    __syncthreads();
#pragma unroll
    for (int s = 128; s > 0; s >>= 1) {
        if (tid < s) red[tid] += red[tid + s];
        __syncthreads();
    }
    const float inv = 1.0f / red[0];

    if (tid < ROWS_PER_BLK)
        out[row_base + tid] = __expf(s_sc[tid] - M) * inv;

    // ---------------- reset counters for next graph replay ------------------
    __threadfence();
    __syncthreads();
    if (tid == 0) {
        unsigned d = atomicAdd(&g_done, 1u) + 1;
        if (d == GRID) {
            g_bar = 0;
            g_done = 0;
            __threadfence();
        }
    }
}

// ---------------------------------------------------------------------------
extern "C" void kernel_launch(void* const* d_in, const int* in_sizes, int n_in,
                              void* d_out, int out_size) {
    const float* hidden = (const float*)d_in[0];   // [H]
    const float* enc    = (const float*)d_in[1];   // [S, H]
    const float* W      = (const float*)d_in[2];   // [H, H]
    float* out          = (float*)d_out;           // [S]

    cudaFuncSetAttribute(fused_kernel,
                         cudaFuncAttributeMaxDynamicSharedMemorySize, SMEM_DYN);
    fused_kernel<<<GRID, BLK, SMEM_DYN>>>(W, hidden, enc, out);
}